// round 16
// baseline (speedup 1.0000x reference)
#include <cuda_runtime.h>
#include <math.h>
#include <stdint.h>

#define NBATCH 4
#define NPTS   8192
#define NP     32768   // NBATCH*NPTS
#define KNN    16

#define KT      128            // knn threads per block
#define CWL     1280           // cache wing (sorted positions) each side
#define CWN     (128 + 2*CWL)  // 2688 cached positions per block
#define RING2   32             // ring slots per thread
#define KNN_SMEM (CWN*16 + RING2*KT*8)   // 43008 + 32768 = 75776 B

// ---------------- scratch (static device globals; no allocs allowed) ----------------
__device__ float4 g_coords4[NP];    // {x, y, z_eff, |p|^2}  (original order)
__device__ float4 g_sx[NP];         // sorted by z_eff within each batch
__device__ int    g_sidx[NP];       // sorted pos -> original index (within batch)
__device__ float g_act1[NP*80];     // tf32-rounded [f0(64) | coords(3) | zeros(13)]
__device__ int   g_idx[NP*KNN];     // global neighbor indices
__device__ float g_Wc1[80*256];     // tf32-rounded combined stage-1 weights
__device__ float g_bc1[256];
__device__ float g_Wc2[144*512];    // tf32-rounded
__device__ float g_bc2[512];
__device__ float g_Wh1[256*256];    // tf32-rounded copy of h1_w rows [0,256)
__device__ float g_ac1[NP*256];     // [a1(128) | c1(128)]
__device__ float g_act2[NP*144];    // tf32-rounded [f1(128) | coords(3) | zeros(13)]
__device__ float g_ac2[NP*512];     // [a2(256) | c2(256)]
__device__ float g_f2[NP*256];      // tf32-rounded
__device__ float g_h[NP*256];
__device__ int   g_gmax[NBATCH*256];
__device__ float g_tvec[NBATCH*256];

// ---------------- tf32 helpers ----------------
__device__ __forceinline__ float tf32r(float f) {
    uint32_t u; asm("cvt.rna.tf32.f32 %0, %1;" : "=r"(u) : "f"(f));
    return __uint_as_float(u);
}
__device__ __forceinline__ void mma_tf32(float* c, const uint32_t* a, uint32_t b0, uint32_t b1) {
    asm volatile("mma.sync.aligned.m16n8k8.row.col.f32.tf32.tf32.f32 "
        "{%0,%1,%2,%3}, {%4,%5,%6,%7}, {%8,%9}, {%0,%1,%2,%3};"
        : "+f"(c[0]), "+f"(c[1]), "+f"(c[2]), "+f"(c[3])
        : "r"(a[0]), "r"(a[1]), "r"(a[2]), "r"(a[3]), "r"(b0), "r"(b1));
}

// ---------------- build combined weights (tf32-rounded) ----------------
__global__ void build_weights(const float* __restrict__ b1w, const float* __restrict__ b1b,
                              const float* __restrict__ b2w, const float* __restrict__ b2b,
                              const float* __restrict__ h1w) {
    int t = threadIdx.x;
    for (int i = t; i < 80*256; i += 256) {
        int k = i >> 8, n = i & 255;
        int nc = n & 127; bool isC = n >= 128;
        float v = 0.f;
        if (k < 64) {
            float wa = b1w[k*128 + nc];
            float wb = b1w[(64+k)*128 + nc];
            v = isC ? wb : (wa - wb);
        } else if (k < 67) {
            float wp = b1w[(128 + (k-64))*128 + nc];
            v = isC ? wp : -wp;
        }
        g_Wc1[i] = tf32r(v);
    }
    for (int n = t; n < 256; n += 256) g_bc1[n] = (n < 128) ? b1b[n] : 0.f;
    for (int i = t; i < 144*512; i += 256) {
        int k = i >> 9, n = i & 511;
        int nc = n & 255; bool isC = n >= 256;
        float v = 0.f;
        if (k < 128) {
            float wa = b2w[k*256 + nc];
            float wb = b2w[(128+k)*256 + nc];
            v = isC ? wb : (wa - wb);
        } else if (k < 131) {
            float wp = b2w[(256 + (k-128))*256 + nc];
            v = isC ? wp : -wp;
        }
        g_Wc2[i] = tf32r(v);
    }
    for (int n = t; n < 512; n += 256) g_bc2[n] = (n < 256) ? b2b[n] : 0.f;
    for (int i = t; i < 256*256; i += 256) g_Wh1[i] = tf32r(h1w[i]);
}

// ---------------- prep: coords + stem (act1 tf32-rounded) ----------------
__global__ void prep_kernel(const float* __restrict__ x,
                            const float* __restrict__ pa, const float* __restrict__ pb,
                            const float* __restrict__ pc,
                            const float* __restrict__ sw, const float* __restrict__ sb) {
    __shared__ float w[256];
    __shared__ float bsh[64];
    if (threadIdx.x < 256) w[threadIdx.x] = sw[threadIdx.x];
    if (threadIdx.x < 64)  bsh[threadIdx.x] = sb[threadIdx.x];
    __syncthreads();
    int i = blockIdx.x * blockDim.x + threadIdx.x;
    if (i >= NP) return;
    float4 xv = ((const float4*)x)[i];
    float z = (*pa) * xv.z + (*pb) * xv.w + (*pc);
    float nsq = fmaf(xv.x, xv.x, fmaf(xv.y, xv.y, z*z));
    g_coords4[i] = make_float4(xv.x, xv.y, z, nsq);
    float* a = &g_act1[i*80];
    #pragma unroll 8
    for (int o = 0; o < 64; o++) {
        float s = bsh[o];
        s = fmaf(xv.x, w[o],      s);
        s = fmaf(xv.y, w[64+o],   s);
        s = fmaf(xv.z, w[128+o],  s);
        s = fmaf(xv.w, w[192+o],  s);
        a[o] = tf32r(fmaxf(s, 0.f));
    }
    a[64] = tf32r(xv.x); a[65] = tf32r(xv.y); a[66] = tf32r(z);
    #pragma unroll
    for (int o = 67; o < 80; o++) a[o] = 0.f;
}

// ---------------- per-batch bitonic sort by z_eff ----------------
__global__ void sort_kernel() {
    extern __shared__ unsigned long long key[];   // NPTS u64
    int b = blockIdx.x;
    int base = b*NPTS;
    for (int i = threadIdx.x; i < NPTS; i += blockDim.x) {
        float z = g_coords4[base + i].z;
        unsigned u = __float_as_uint(z);
        u = (u & 0x80000000u) ? ~u : (u | 0x80000000u);   // monotone key
        key[i] = ((unsigned long long)u << 32) | (unsigned)i;
    }
    __syncthreads();
    for (int k = 2; k <= NPTS; k <<= 1) {
        for (int j = k >> 1; j > 0; j >>= 1) {
            for (int i = threadIdx.x; i < NPTS; i += blockDim.x) {
                int p = i ^ j;
                if (p > i) {
                    bool up = ((i & k) == 0);
                    unsigned long long a = key[i], c = key[p];
                    if ((a > c) == up) { key[i] = c; key[p] = a; }
                }
            }
            __syncthreads();
        }
    }
    for (int i = threadIdx.x; i < NPTS; i += blockDim.x) {
        int oi = (int)(key[i] & 0xFFFFFFFFu);
        g_sx[base + i] = g_coords4[base + oi];
        g_sidx[base + i] = oi;
    }
}

// ---------------- KNN on sorted order: outward scan with exact z-pruning ----------------
// Surrogate d' = |p|^2 - 2 q.p; d_true^2 = d' + |q|^2 >= dz^2 (sorted axis).
// Seed: 16th-smallest over +/-32 sorted window -> valid upper-bound threshold.
// Scan 128-cand chunks outward (both sides); predicated ring push; drain per
// iteration; ring overflow -> discard ring, exact branchy rescan of the chunks.
// Side pruned exactly when nearest unscanned dz^2 >= worst + |q|^2.
__global__ __launch_bounds__(KT) void knn_sorted_kernel() {
    extern __shared__ char sm[];
    float4* cache  = (float4*)sm;                          // CWN float4
    float*  ring_d = (float*)(sm + CWN*16);                // [RING2][KT]
    int*    ring_i = (int*)  (sm + CWN*16 + RING2*KT*4);   // [RING2][KT]

    int b    = blockIdx.x >> 6;
    int s0   = (blockIdx.x & 63) * KT;
    int base = b*NPTS;
    int c0   = s0 - CWL;

    // cooperative cache load (OOB -> inert sentinel: d = 3e37, never accepted)
    for (int i = threadIdx.x; i < CWN; i += KT) {
        int pos = c0 + i;
        float4 v = (pos >= 0 && pos < NPTS) ? g_sx[base + pos]
                                            : make_float4(0.f, 0.f, 0.f, 3.0e37f);
        cache[i] = v;
    }
    __syncthreads();

    int s = s0 + threadIdx.x;
    float4 q = cache[s - c0];
    float nqx = -2.f*q.x, nqy = -2.f*q.y, nqz = -2.f*q.z;
    float qn = q.w;

    // ---- seed threshold: 16th smallest over [s-32, s+32) ----
    float snet[KNN];
    #pragma unroll
    for (int t = 0; t < KNN; t++) snet[t] = 3.4e38f;
    int lo = max(0, s - 32), hi = min(NPTS, s + 32);
    for (int pos = lo; pos < hi; pos++) {
        float4 p = cache[pos - c0];
        float d = fmaf(p.z, nqz, fmaf(p.y, nqy, fmaf(p.x, nqx, p.w)));
        #pragma unroll
        for (int t = 0; t < KNN; t++) {
            float l2 = fminf(snet[t], d);
            d = fmaxf(snet[t], d);
            snet[t] = l2;
        }
    }
    float tau = snet[KNN-1];
    int tb = __float_as_int(tau);
    tb += (tau >= 0.f) ? 1 : -1;          // nextafter(tau, +inf)
    float worst = __int_as_float(tb);

    float bd[KNN]; int bi[KNN];
    #pragma unroll
    for (int t = 0; t < KNN; t++) { bd[t] = worst; bi[t] = s; }

    int cnt = 0, ovf = 0;

    auto scan_chunk = [&](int a) {
        bool inc = (a >= c0) && (a + 128 <= c0 + CWN);
        if (inc) {
            const float4* cp = &cache[a - c0];
            #pragma unroll 4
            for (int j = 0; j < 128; j++) {
                float4 p = cp[j];
                float d = fmaf(p.z, nqz, fmaf(p.y, nqy, fmaf(p.x, nqx, p.w)));
                if (d < worst) {
                    if (cnt < RING2) {
                        ring_d[cnt*KT + threadIdx.x] = d;
                        ring_i[cnt*KT + threadIdx.x] = a + j;
                        cnt++;
                    } else ovf = 1;
                }
            }
        } else {
            #pragma unroll 4
            for (int j = 0; j < 128; j++) {
                int pos = a + j;
                bool inb = (pos >= 0) && (pos < NPTS);
                float4 p = g_sx[base + (inb ? pos : 0)];
                float d = fmaf(p.z, nqz, fmaf(p.y, nqy, fmaf(p.x, nqx, p.w)));
                if (inb && d < worst) {
                    if (cnt < RING2) {
                        ring_d[cnt*KT + threadIdx.x] = d;
                        ring_i[cnt*KT + threadIdx.x] = pos;
                        cnt++;
                    } else ovf = 1;
                }
            }
        }
    };
    auto rescan_chunk = [&](int a) {
        bool inc = (a >= c0) && (a + 128 <= c0 + CWN);
        for (int j = 0; j < 128; j++) {
            int pos = a + j;
            float d;
            if (inc) {
                float4 p = cache[pos - c0];
                d = fmaf(p.z, nqz, fmaf(p.y, nqy, fmaf(p.x, nqx, p.w)));
            } else {
                bool inb = (pos >= 0) && (pos < NPTS);
                float4 p = g_sx[base + (inb ? pos : 0)];
                d = inb ? fmaf(p.z, nqz, fmaf(p.y, nqy, fmaf(p.x, nqx, p.w))) : 3.4e38f;
            }
            float w = bd[0]; int ws = 0;
            #pragma unroll
            for (int t = 1; t < KNN; t++) if (bd[t] > w) { w = bd[t]; ws = t; }
            if (d < w) { bd[ws] = d; bi[ws] = pos; }
        }
    };
    auto zAt = [&](int pos) -> float {
        return (pos >= c0 && pos < c0 + CWN) ? cache[pos - c0].z : g_sx[base + pos].z;
    };

    int lw = 0, rw = 0;
    bool lact = true, ract = true;
    for (int it = 0; it < 64 && (lact || ract); it++) {
        cnt = 0; ovf = 0;
        int aR = s + 128*rw;
        int aL = s - 128*(lw + 1);
        bool dR = ract, dL = lact;
        if (dR) { scan_chunk(aR); rw++; }
        if (dL) { scan_chunk(aL); lw++; }
        if (ovf) {
            if (dR) rescan_chunk(aR);
            if (dL) rescan_chunk(aL);
        } else {
            for (int k = 0; k < cnt; k++) {
                float d = ring_d[k*KT + threadIdx.x];
                int  ji = ring_i[k*KT + threadIdx.x];
                float w = bd[0]; int ws = 0;
                #pragma unroll
                for (int t = 1; t < KNN; t++) if (bd[t] > w) { w = bd[t]; ws = t; }
                if (d < w) { bd[ws] = d; bi[ws] = ji; }
            }
        }
        float w = bd[0];
        #pragma unroll
        for (int t = 1; t < KNN; t++) w = fmaxf(w, bd[t]);
        worst = w;
        if (ract) {
            int pn = s + 128*rw;
            if (pn >= NPTS) ract = false;
            else { float dz = zAt(pn) - q.z; ract = (dz*dz < worst + qn); }
        }
        if (lact) {
            int pn = s - 128*lw - 1;
            if (pn < 0) lact = false;
            else { float dz = q.z - zAt(pn); lact = (dz*dz < worst + qn); }
        }
    }

    int oq = g_sidx[base + s];
    int qg = base + oq;
    #pragma unroll
    for (int t = 0; t < KNN; t++) g_idx[qg*KNN + t] = base + g_sidx[base + bi[t]];
}

// ---------------- tf32 tensor-core GEMM: C[M,NT] = act(A@W + bias) ----------------
// BM=128, BN=64, BK=16, 256 threads = 8 warps (4m x 2n), warp tile 32x32,
// mma.sync.m16n8k8 tf32 with fp32 accum. A and W must be tf32-pre-rounded.
// BIASMODE 0: bias[n]; 1: bias[(row>>13)*256 + n]
template<int KP, int NT, int BIASMODE, int RELU>
__global__ __launch_bounds__(256) void gemm_kernel(const float* __restrict__ A,
                                                   const float* __restrict__ W,
                                                   const float* __restrict__ bias,
                                                   float* __restrict__ C) {
    __shared__ float As[16][136];   // k-major; 136%32==8 -> conflict-free frag loads
    __shared__ float Bs[16][72];    // 72%32==8
    int tid = threadIdx.x;
    int warp = tid >> 5, lane = tid & 31;
    int wm = warp & 3, wn = warp >> 2;
    int grp = lane >> 2, tig = lane & 3;
    int row0 = blockIdx.x * 128;
    int col0 = blockIdx.y * 64;
    float acc[2][4][4];
    #pragma unroll
    for (int mt = 0; mt < 2; mt++)
        #pragma unroll
        for (int nt = 0; nt < 4; nt++)
            #pragma unroll
            for (int r = 0; r < 4; r++) acc[mt][nt][r] = 0.f;

    for (int k0 = 0; k0 < KP; k0 += 16) {
        #pragma unroll
        for (int i = 0; i < 2; i++) {
            int lin = tid + i*256;
            int r = lin >> 2, kc = (lin & 3) * 4;
            float4 av = *(const float4*)&A[(row0 + r)*KP + k0 + kc];
            As[kc+0][r] = av.x; As[kc+1][r] = av.y;
            As[kc+2][r] = av.z; As[kc+3][r] = av.w;
        }
        {
            int kk = tid >> 4, cc = (tid & 15) * 4;
            float4 wv = *(const float4*)&W[(k0 + kk)*NT + col0 + cc];
            Bs[kk][cc+0] = wv.x; Bs[kk][cc+1] = wv.y;
            Bs[kk][cc+2] = wv.z; Bs[kk][cc+3] = wv.w;
        }
        __syncthreads();
        #pragma unroll
        for (int ks = 0; ks < 16; ks += 8) {
            uint32_t af[2][4];
            #pragma unroll
            for (int mt = 0; mt < 2; mt++) {
                int r = wm*32 + mt*16 + grp;
                af[mt][0] = __float_as_uint(As[ks+tig][r]);
                af[mt][1] = __float_as_uint(As[ks+tig][r+8]);
                af[mt][2] = __float_as_uint(As[ks+tig+4][r]);
                af[mt][3] = __float_as_uint(As[ks+tig+4][r+8]);
            }
            #pragma unroll
            for (int nt = 0; nt < 4; nt++) {
                int nn = wn*32 + nt*8 + grp;
                uint32_t b0 = __float_as_uint(Bs[ks+tig][nn]);
                uint32_t b1 = __float_as_uint(Bs[ks+tig+4][nn]);
                mma_tf32(acc[0][nt], af[0], b0, b1);
                mma_tf32(acc[1][nt], af[1], b0, b1);
            }
        }
        __syncthreads();
    }
    #pragma unroll
    for (int mt = 0; mt < 2; mt++) {
        int row = row0 + wm*32 + mt*16 + grp;
        #pragma unroll
        for (int nt = 0; nt < 4; nt++) {
            int col = col0 + wn*32 + nt*8 + tig*2;
            float bx0 = (BIASMODE == 0) ? bias[col]   : bias[(row >> 13)*256 + col];
            float bx1 = (BIASMODE == 0) ? bias[col+1] : bias[(row >> 13)*256 + col + 1];
            float v0 = acc[mt][nt][0] + bx0, v1 = acc[mt][nt][1] + bx1;
            float v2 = acc[mt][nt][2] + bx0, v3 = acc[mt][nt][3] + bx1;
            if (RELU) {
                v0 = fmaxf(v0, 0.f); v1 = fmaxf(v1, 0.f);
                v2 = fmaxf(v2, 0.f); v3 = fmaxf(v3, 0.f);
            }
            *(float2*)&C[row*NT + col]       = make_float2(v0, v1);
            *(float2*)&C[(row+8)*NT + col]   = make_float2(v2, v3);
        }
    }
}

// ---------------- gather-max stage 1 (act2 tf32-rounded) ----------------
__global__ void gather1_kernel() {
    int wid  = (blockIdx.x * blockDim.x + threadIdx.x) >> 5;
    int lane = threadIdx.x & 31;
    if (wid >= NP) return;
    const int* idx = &g_idx[wid*KNN];
    float4 mv = make_float4(-3.4e38f, -3.4e38f, -3.4e38f, -3.4e38f);
    #pragma unroll
    for (int t = 0; t < KNN; t++) {
        int j = idx[t];
        float4 v = *(const float4*)&g_ac1[j*256 + 128 + lane*4];
        mv.x = fmaxf(mv.x, v.x); mv.y = fmaxf(mv.y, v.y);
        mv.z = fmaxf(mv.z, v.z); mv.w = fmaxf(mv.w, v.w);
    }
    float4 a = *(const float4*)&g_ac1[wid*256 + lane*4];
    float4 o;
    o.x = tf32r(fmaxf(a.x + mv.x, 0.f)); o.y = tf32r(fmaxf(a.y + mv.y, 0.f));
    o.z = tf32r(fmaxf(a.z + mv.z, 0.f)); o.w = tf32r(fmaxf(a.w + mv.w, 0.f));
    *(float4*)&g_act2[wid*144 + lane*4] = o;
    if (lane < 16) {
        float v = (lane < 3) ? tf32r(((const float*)g_coords4)[wid*4 + lane]) : 0.f;
        g_act2[wid*144 + 128 + lane] = v;
    }
}

// ---------------- gather-max stage 2 (f2 tf32-rounded) ----------------
__global__ void gather2_kernel() {
    int wid  = (blockIdx.x * blockDim.x + threadIdx.x) >> 5;
    int lane = threadIdx.x & 31;
    if (wid >= NP) return;
    const int* idx = &g_idx[wid*KNN];
    float4 m0 = make_float4(-3.4e38f, -3.4e38f, -3.4e38f, -3.4e38f);
    float4 m1 = m0;
    #pragma unroll
    for (int t = 0; t < KNN; t++) {
        int j = idx[t];
        float4 v0 = *(const float4*)&g_ac2[j*512 + 256 + lane*4];
        float4 v1 = *(const float4*)&g_ac2[j*512 + 384 + lane*4];
        m0.x = fmaxf(m0.x, v0.x); m0.y = fmaxf(m0.y, v0.y);
        m0.z = fmaxf(m0.z, v0.z); m0.w = fmaxf(m0.w, v0.w);
        m1.x = fmaxf(m1.x, v1.x); m1.y = fmaxf(m1.y, v1.y);
        m1.z = fmaxf(m1.z, v1.z); m1.w = fmaxf(m1.w, v1.w);
    }
    float4 a0 = *(const float4*)&g_ac2[wid*512 + lane*4];
    float4 a1 = *(const float4*)&g_ac2[wid*512 + 128 + lane*4];
    float4 o0, o1;
    o0.x = tf32r(fmaxf(a0.x + m0.x, 0.f)); o0.y = tf32r(fmaxf(a0.y + m0.y, 0.f));
    o0.z = tf32r(fmaxf(a0.z + m0.z, 0.f)); o0.w = tf32r(fmaxf(a0.w + m0.w, 0.f));
    o1.x = tf32r(fmaxf(a1.x + m1.x, 0.f)); o1.y = tf32r(fmaxf(a1.y + m1.y, 0.f));
    o1.z = tf32r(fmaxf(a1.z + m1.z, 0.f)); o1.w = tf32r(fmaxf(a1.w + m1.w, 0.f));
    *(float4*)&g_f2[wid*256 + lane*4]       = o0;
    *(float4*)&g_f2[wid*256 + 128 + lane*4] = o1;
}

// ---------------- global max pooling ----------------
__global__ void zero_gmax_kernel() {
    int i = threadIdx.x;
    if (i < NBATCH*256) g_gmax[i] = 0;   // 0.0f bits; all f2 >= 0
}

__global__ void colmax_kernel() {
    int b = blockIdx.x >> 5;
    int chunk = blockIdx.x & 31;
    int c = threadIdx.x;
    int base = b*NPTS + chunk*256;
    float m = 0.f;
    #pragma unroll 4
    for (int p = 0; p < 256; p++) m = fmaxf(m, g_f2[(base + p)*256 + c]);
    atomicMax(&g_gmax[b*256 + c], __float_as_int(m));
}

// ---------------- per-batch vectors ----------------
__global__ void batchvec_kernel(const float* __restrict__ globw, const float* __restrict__ globb,
                                const float* __restrict__ h1w, const float* __restrict__ h1b) {
    int b = blockIdx.x, n = threadIdx.x;
    __shared__ float gm[256], gg[256];
    gm[n] = __int_as_float(g_gmax[b*256 + n]);
    __syncthreads();
    float s = globb[n];
    #pragma unroll 8
    for (int k = 0; k < 256; k++) s = fmaf(gm[k], globw[k*256 + n], s);
    gg[n] = fmaxf(s, 0.f);
    __syncthreads();
    float t = h1b[n];
    #pragma unroll 8
    for (int k = 0; k < 256; k++) t = fmaf(gg[k], h1w[(256 + k)*256 + n], t);
    g_tvec[b*256 + n] = t;
}

// ---------------- final head ----------------
__global__ void final_kernel(const float* __restrict__ x,
                             const float* __restrict__ h2w, const float* __restrict__ h2b,
                             const float* __restrict__ pthresh, const float* __restrict__ psharp,
                             const float* __restrict__ pscale, float* __restrict__ out) {
    int wid  = (blockIdx.x * blockDim.x + threadIdx.x) >> 5;
    int lane = threadIdx.x & 31;
    if (wid >= NP) return;
    const float* h = &g_h[wid*256];
    float s0 = 0.f, s1 = 0.f, s2 = 0.f;
    #pragma unroll
    for (int m = 0; m < 8; m++) {
        int k = lane + 32*m;
        float hv = h[k];
        s0 = fmaf(hv, h2w[k*3+0], s0);
        s1 = fmaf(hv, h2w[k*3+1], s1);
        s2 = fmaf(hv, h2w[k*3+2], s2);
    }
    #pragma unroll
    for (int o = 16; o; o >>= 1) {
        s0 += __shfl_down_sync(0xFFFFFFFFu, s0, o);
        s1 += __shfl_down_sync(0xFFFFFFFFu, s1, o);
        s2 += __shfl_down_sync(0xFFFFFFFFu, s2, o);
    }
    if (lane == 0) {
        float hag = x[wid*4 + 3];
        float t = (*psharp) * ((*pthresh) - hag);
        float bias = (*pscale) / (1.f + expf(-t));
        out[wid*3+0] = s0 + h2b[0] + bias;
        out[wid*3+1] = s1 + h2b[1];
        out[wid*3+2] = s2 + h2b[2];
    }
}

// ---------------- launch ----------------
extern "C" void kernel_launch(void* const* d_in, const int* in_sizes, int n_in,
                              void* d_out, int out_size) {
    const float* x      = (const float*)d_in[0];
    const float* hmix_a = (const float*)d_in[1];
    const float* hmix_b = (const float*)d_in[2];
    const float* hmix_c = (const float*)d_in[3];
    const float* stem_w = (const float*)d_in[4];
    const float* stem_b = (const float*)d_in[5];
    const float* b1_w   = (const float*)d_in[6];
    const float* b1_b   = (const float*)d_in[7];
    const float* b2_w   = (const float*)d_in[8];
    const float* b2_b   = (const float*)d_in[9];
    const float* glob_w = (const float*)d_in[10];
    const float* glob_b = (const float*)d_in[11];
    const float* h1_w   = (const float*)d_in[12];
    const float* h1_b   = (const float*)d_in[13];
    const float* h2_w   = (const float*)d_in[14];
    const float* h2_b   = (const float*)d_in[15];
    const float* thresh = (const float*)d_in[16];
    const float* sharp  = (const float*)d_in[17];
    const float* scale  = (const float*)d_in[18];
    float* out = (float*)d_out;

    void *p_act1, *p_Wc1, *p_bc1, *p_ac1, *p_act2, *p_Wc2, *p_bc2, *p_ac2, *p_f2, *p_tvec, *p_h, *p_Wh1;
    cudaGetSymbolAddress(&p_act1, g_act1);
    cudaGetSymbolAddress(&p_Wc1,  g_Wc1);
    cudaGetSymbolAddress(&p_bc1,  g_bc1);
    cudaGetSymbolAddress(&p_ac1,  g_ac1);
    cudaGetSymbolAddress(&p_act2, g_act2);
    cudaGetSymbolAddress(&p_Wc2,  g_Wc2);
    cudaGetSymbolAddress(&p_bc2,  g_bc2);
    cudaGetSymbolAddress(&p_ac2,  g_ac2);
    cudaGetSymbolAddress(&p_f2,   g_f2);
    cudaGetSymbolAddress(&p_tvec, g_tvec);
    cudaGetSymbolAddress(&p_h,    g_h);
    cudaGetSymbolAddress(&p_Wh1,  g_Wh1);

    cudaFuncSetAttribute(sort_kernel, cudaFuncAttributeMaxDynamicSharedMemorySize, NPTS*8);
    cudaFuncSetAttribute(knn_sorted_kernel, cudaFuncAttributeMaxDynamicSharedMemorySize, KNN_SMEM);

    build_weights<<<1, 256>>>(b1_w, b1_b, b2_w, b2_b, h1_w);
    prep_kernel<<<NP/256, 256>>>(x, hmix_a, hmix_b, hmix_c, stem_w, stem_b);
    zero_gmax_kernel<<<1, 1024>>>();
    sort_kernel<<<NBATCH, 1024, NPTS*8>>>();
    knn_sorted_kernel<<<NBATCH*64, KT, KNN_SMEM>>>();

    gemm_kernel<80, 256, 0, 0><<<dim3(NP/128, 256/64), 256>>>(
        (const float*)p_act1, (const float*)p_Wc1, (const float*)p_bc1, (float*)p_ac1);
    gather1_kernel<<<NP*32/256, 256>>>();

    gemm_kernel<144, 512, 0, 0><<<dim3(NP/128, 512/64), 256>>>(
        (const float*)p_act2, (const float*)p_Wc2, (const float*)p_bc2, (float*)p_ac2);
    gather2_kernel<<<NP*32/256, 256>>>();

    colmax_kernel<<<NBATCH*32, 256>>>();
    batchvec_kernel<<<NBATCH, 256>>>(glob_w, glob_b, h1_w, h1_b);

    gemm_kernel<256, 256, 1, 1><<<dim3(NP/128, 256/64), 256>>>(
        (const float*)p_f2, (const float*)p_Wh1, (const float*)p_tvec, (float*)p_h);

    final_kernel<<<NP*32/256, 256>>>(x, h2_w, h2_b, thresh, sharp, scale, out);
    (void)in_sizes; (void)n_in; (void)out_size;
}

// round 17
// speedup vs baseline: 1.5352x; 1.5352x over previous
#include <cuda_runtime.h>
#include <math.h>
#include <stdint.h>

#define NBATCH 4
#define NPTS   8192
#define NP     32768   // NBATCH*NPTS
#define KNN    16

#define KT      128            // knn threads per block
#define KCHUNK  2048           // candidates per smem tile
#define NCHUNK  (NPTS/KCHUNK)  // 4
#define NACHUNK 2              // chunks used for phase-A threshold (exactness: any 16 distinct cands bound the 16th)
#define KBLK    128            // block size for phase-A minima
#define RP      16             // ring slots per stream per chunk
#define NSTREAM 4
#define RING    (RP*NSTREAM)   // 64
#define KNN_SMEM (KCHUNK*16 + RING*KT*4 + RING*KT*4)   // 32KB + 32KB + 32KB = 96KB

// ---------------- scratch (static device globals; no allocs allowed) ----------------
__device__ float4 g_coords4[NP];    // {x, y, z, |p|^2}  (full fp32 for KNN)
__device__ float g_act1[NP*80];     // tf32-rounded [f0(64) | coords(3) | zeros(13)]
__device__ int   g_idx[NP*KNN];     // global neighbor indices
__device__ float g_Wc1[80*256];     // tf32-rounded combined stage-1 weights
__device__ float g_bc1[256];
__device__ float g_Wc2[144*512];    // tf32-rounded
__device__ float g_bc2[512];
__device__ float g_Wh1[256*256];    // tf32-rounded copy of h1_w rows [0,256)
__device__ float g_ac1[NP*256];     // [a1(128) | c1(128)]
__device__ float g_act2[NP*144];    // tf32-rounded [f1(128) | coords(3) | zeros(13)]
__device__ float g_ac2[NP*512];     // [a2(256) | c2(256)]
__device__ float g_f2[NP*256];      // tf32-rounded
__device__ float g_h[NP*256];
__device__ int   g_gmax[NBATCH*256];
__device__ float g_tvec[NBATCH*256];

// ---------------- tf32 helpers ----------------
__device__ __forceinline__ float tf32r(float f) {
    uint32_t u; asm("cvt.rna.tf32.f32 %0, %1;" : "=r"(u) : "f"(f));
    return __uint_as_float(u);
}
__device__ __forceinline__ void mma_tf32(float* c, const uint32_t* a, uint32_t b0, uint32_t b1) {
    asm volatile("mma.sync.aligned.m16n8k8.row.col.f32.tf32.tf32.f32 "
        "{%0,%1,%2,%3}, {%4,%5,%6,%7}, {%8,%9}, {%0,%1,%2,%3};"
        : "+f"(c[0]), "+f"(c[1]), "+f"(c[2]), "+f"(c[3])
        : "r"(a[0]), "r"(a[1]), "r"(a[2]), "r"(a[3]), "r"(b0), "r"(b1));
}

// ---------------- build combined weights (tf32-rounded) ----------------
__global__ void build_weights(const float* __restrict__ b1w, const float* __restrict__ b1b,
                              const float* __restrict__ b2w, const float* __restrict__ b2b,
                              const float* __restrict__ h1w) {
    int t = threadIdx.x;
    for (int i = t; i < 80*256; i += 256) {
        int k = i >> 8, n = i & 255;
        int nc = n & 127; bool isC = n >= 128;
        float v = 0.f;
        if (k < 64) {
            float wa = b1w[k*128 + nc];
            float wb = b1w[(64+k)*128 + nc];
            v = isC ? wb : (wa - wb);
        } else if (k < 67) {
            float wp = b1w[(128 + (k-64))*128 + nc];
            v = isC ? wp : -wp;
        }
        g_Wc1[i] = tf32r(v);
    }
    for (int n = t; n < 256; n += 256) g_bc1[n] = (n < 128) ? b1b[n] : 0.f;
    for (int i = t; i < 144*512; i += 256) {
        int k = i >> 9, n = i & 511;
        int nc = n & 255; bool isC = n >= 256;
        float v = 0.f;
        if (k < 128) {
            float wa = b2w[k*256 + nc];
            float wb = b2w[(128+k)*256 + nc];
            v = isC ? wb : (wa - wb);
        } else if (k < 131) {
            float wp = b2w[(256 + (k-128))*256 + nc];
            v = isC ? wp : -wp;
        }
        g_Wc2[i] = tf32r(v);
    }
    for (int n = t; n < 512; n += 256) g_bc2[n] = (n < 256) ? b2b[n] : 0.f;
    for (int i = t; i < 256*256; i += 256) g_Wh1[i] = tf32r(h1w[i]);
}

// ---------------- prep: coords + stem (act1 tf32-rounded) ----------------
__global__ void prep_kernel(const float* __restrict__ x,
                            const float* __restrict__ pa, const float* __restrict__ pb,
                            const float* __restrict__ pc,
                            const float* __restrict__ sw, const float* __restrict__ sb) {
    __shared__ float w[256];
    __shared__ float bsh[64];
    if (threadIdx.x < 256) w[threadIdx.x] = sw[threadIdx.x];
    if (threadIdx.x < 64)  bsh[threadIdx.x] = sb[threadIdx.x];
    __syncthreads();
    int i = blockIdx.x * blockDim.x + threadIdx.x;
    if (i >= NP) return;
    float4 xv = ((const float4*)x)[i];
    float z = (*pa) * xv.z + (*pb) * xv.w + (*pc);
    float nsq = fmaf(xv.x, xv.x, fmaf(xv.y, xv.y, z*z));
    g_coords4[i] = make_float4(xv.x, xv.y, z, nsq);
    float* a = &g_act1[i*80];
    #pragma unroll 8
    for (int o = 0; o < 64; o++) {
        float s = bsh[o];
        s = fmaf(xv.x, w[o],      s);
        s = fmaf(xv.y, w[64+o],   s);
        s = fmaf(xv.z, w[128+o],  s);
        s = fmaf(xv.w, w[192+o],  s);
        a[o] = tf32r(fmaxf(s, 0.f));
    }
    a[64] = tf32r(xv.x); a[65] = tf32r(xv.y); a[66] = tf32r(z);
    #pragma unroll
    for (int o = 67; o < 80; o++) a[o] = 0.f;
}

// ---------------- KNN: two-phase threshold + 4-stream ring collection ----------------
// Surrogate d' = |p|^2 - 2 q.p (monotone per query in true distance).
// Phase A: block-minima over the FIRST 2 chunks only -> tau = 16th smallest of 32
// block-minima. Exact upper bound on the true 16th: the 16 selected minima are 16
// distinct candidates with d <= tau. Phase B scans all 4 chunks with replace-worst.
__global__ __launch_bounds__(KT) void knn_kernel() {
    extern __shared__ char sm[];
    float4* tile   = (float4*)sm;                              // KCHUNK float4
    float*  ring_d = (float*)(sm + KCHUNK*16);                 // [RING][KT]
    int*    ring_i = (int*)  (sm + KCHUNK*16 + RING*KT*4);     // [RING][KT]

    int b    = blockIdx.x >> 6;                 // 64 query-blocks per batch
    int n    = (blockIdx.x & 63)*KT + threadIdx.x;
    int base = b*NPTS;
    float4 q = g_coords4[base + n];
    float nqx = -2.f*q.x, nqy = -2.f*q.y, nqz = -2.f*q.z;

    // ---- Phase A: threshold from chunks [0, NACHUNK) ----
    float s[KNN];
    #pragma unroll
    for (int t = 0; t < KNN; t++) s[t] = 3.4e38f;

    for (int c = 0; c < NACHUNK; c++) {
        __syncthreads();
        for (int i = threadIdx.x; i < KCHUNK; i += KT)
            tile[i] = g_coords4[base + c*KCHUNK + i];
        __syncthreads();
        for (int blk = 0; blk < KCHUNK/KBLK; blk++) {
            const float4* tb = &tile[blk*KBLK];
            float m0 = 3.4e38f, m1 = 3.4e38f, m2 = 3.4e38f, m3 = 3.4e38f;
            #pragma unroll 4
            for (int j = 0; j < KBLK; j += 4) {
                float4 p0 = tb[j+0], p1 = tb[j+1], p2 = tb[j+2], p3 = tb[j+3];
                m0 = fminf(m0, fmaf(p0.z, nqz, fmaf(p0.y, nqy, fmaf(p0.x, nqx, p0.w))));
                m1 = fminf(m1, fmaf(p1.z, nqz, fmaf(p1.y, nqy, fmaf(p1.x, nqx, p1.w))));
                m2 = fminf(m2, fmaf(p2.z, nqz, fmaf(p2.y, nqy, fmaf(p2.x, nqx, p2.w))));
                m3 = fminf(m3, fmaf(p3.z, nqz, fmaf(p3.y, nqy, fmaf(p3.x, nqx, p3.w))));
            }
            float m = fminf(fminf(m0, m1), fminf(m2, m3));
            // branchless insert into 16 smallest (s ascending)
            #pragma unroll
            for (int t = 0; t < KNN; t++) {
                float lo = fminf(s[t], m);
                m = fmaxf(s[t], m);
                s[t] = lo;
            }
        }
    }
    float tau = s[KNN-1];
    int tb_ = __float_as_int(tau);
    tb_ += (tau >= 0.f) ? 1 : -1;          // nextafter(tau, +inf): accept d <= tau via d < worst
    float worst = __int_as_float(tb_);

    // ---- Phase B: 4-stream collect + drain over all chunks ----
    float bd[KNN]; int bi[KNN];
    #pragma unroll
    for (int t = 0; t < KNN; t++) { bd[t] = worst; bi[t] = 0; }

    for (int c = 0; c < NCHUNK; c++) {
        __syncthreads();
        for (int i = threadIdx.x; i < KCHUNK; i += KT)
            tile[i] = g_coords4[base + c*KCHUNK + i];
        __syncthreads();
        int cnt0 = 0, cnt1 = 0, cnt2 = 0, cnt3 = 0;
        int jbase = c*KCHUNK;
        const int Q = KCHUNK/4;   // 512
        #pragma unroll 2
        for (int j = 0; j < Q; j++) {
            float4 p0 = tile[j];
            float4 p1 = tile[j + Q];
            float4 p2 = tile[j + 2*Q];
            float4 p3 = tile[j + 3*Q];
            float d0 = fmaf(p0.z, nqz, fmaf(p0.y, nqy, fmaf(p0.x, nqx, p0.w)));
            float d1 = fmaf(p1.z, nqz, fmaf(p1.y, nqy, fmaf(p1.x, nqx, p1.w)));
            float d2 = fmaf(p2.z, nqz, fmaf(p2.y, nqy, fmaf(p2.x, nqx, p2.w)));
            float d3 = fmaf(p3.z, nqz, fmaf(p3.y, nqy, fmaf(p3.x, nqx, p3.w)));
            if (d0 < worst && cnt0 < RP) {
                ring_d[(0*RP + cnt0)*KT + threadIdx.x] = d0;
                ring_i[(0*RP + cnt0)*KT + threadIdx.x] = jbase + j;
                cnt0++;
            }
            if (d1 < worst && cnt1 < RP) {
                ring_d[(1*RP + cnt1)*KT + threadIdx.x] = d1;
                ring_i[(1*RP + cnt1)*KT + threadIdx.x] = jbase + j + Q;
                cnt1++;
            }
            if (d2 < worst && cnt2 < RP) {
                ring_d[(2*RP + cnt2)*KT + threadIdx.x] = d2;
                ring_i[(2*RP + cnt2)*KT + threadIdx.x] = jbase + j + 2*Q;
                cnt2++;
            }
            if (d3 < worst && cnt3 < RP) {
                ring_d[(3*RP + cnt3)*KT + threadIdx.x] = d3;
                ring_i[(3*RP + cnt3)*KT + threadIdx.x] = jbase + j + 3*Q;
                cnt3++;
            }
        }
        int cnts[NSTREAM] = {cnt0, cnt1, cnt2, cnt3};
        #pragma unroll
        for (int st = 0; st < NSTREAM; st++) {
            for (int k = 0; k < cnts[st]; k++) {
                float d = ring_d[(st*RP + k)*KT + threadIdx.x];
                int  ji = ring_i[(st*RP + k)*KT + threadIdx.x];
                float w = bd[0]; int ws = 0;
                #pragma unroll
                for (int t = 1; t < KNN; t++) if (bd[t] > w) { w = bd[t]; ws = t; }
                if (d < w) { bd[ws] = d; bi[ws] = ji; }
            }
        }
        float w = bd[0];
        #pragma unroll
        for (int t = 1; t < KNN; t++) w = fmaxf(w, bd[t]);
        worst = w;
    }

    int qg = base + n;
    #pragma unroll
    for (int t = 0; t < KNN; t++) g_idx[qg*KNN + t] = base + bi[t];
}

// ---------------- tf32 tensor-core GEMM: C[M,NT] = act(A@W + bias) ----------------
// BM=128, BN=64, BK=16, 256 threads = 8 warps (4m x 2n), warp tile 32x32,
// mma.sync.m16n8k8 tf32 with fp32 accum. A and W must be tf32-pre-rounded.
// BIASMODE 0: bias[n]; 1: bias[(row>>13)*256 + n]
template<int KP, int NT, int BIASMODE, int RELU>
__global__ __launch_bounds__(256) void gemm_kernel(const float* __restrict__ A,
                                                   const float* __restrict__ W,
                                                   const float* __restrict__ bias,
                                                   float* __restrict__ C) {
    __shared__ float As[16][136];   // k-major; 136%32==8 -> conflict-free frag loads
    __shared__ float Bs[16][72];    // 72%32==8
    int tid = threadIdx.x;
    int warp = tid >> 5, lane = tid & 31;
    int wm = warp & 3, wn = warp >> 2;
    int grp = lane >> 2, tig = lane & 3;
    int row0 = blockIdx.x * 128;
    int col0 = blockIdx.y * 64;
    float acc[2][4][4];
    #pragma unroll
    for (int mt = 0; mt < 2; mt++)
        #pragma unroll
        for (int nt = 0; nt < 4; nt++)
            #pragma unroll
            for (int r = 0; r < 4; r++) acc[mt][nt][r] = 0.f;

    for (int k0 = 0; k0 < KP; k0 += 16) {
        #pragma unroll
        for (int i = 0; i < 2; i++) {
            int lin = tid + i*256;
            int r = lin >> 2, kc = (lin & 3) * 4;
            float4 av = *(const float4*)&A[(row0 + r)*KP + k0 + kc];
            As[kc+0][r] = av.x; As[kc+1][r] = av.y;
            As[kc+2][r] = av.z; As[kc+3][r] = av.w;
        }
        {
            int kk = tid >> 4, cc = (tid & 15) * 4;
            float4 wv = *(const float4*)&W[(k0 + kk)*NT + col0 + cc];
            Bs[kk][cc+0] = wv.x; Bs[kk][cc+1] = wv.y;
            Bs[kk][cc+2] = wv.z; Bs[kk][cc+3] = wv.w;
        }
        __syncthreads();
        #pragma unroll
        for (int ks = 0; ks < 16; ks += 8) {
            uint32_t af[2][4];
            #pragma unroll
            for (int mt = 0; mt < 2; mt++) {
                int r = wm*32 + mt*16 + grp;
                af[mt][0] = __float_as_uint(As[ks+tig][r]);
                af[mt][1] = __float_as_uint(As[ks+tig][r+8]);
                af[mt][2] = __float_as_uint(As[ks+tig+4][r]);
                af[mt][3] = __float_as_uint(As[ks+tig+4][r+8]);
            }
            #pragma unroll
            for (int nt = 0; nt < 4; nt++) {
                int nn = wn*32 + nt*8 + grp;
                uint32_t b0 = __float_as_uint(Bs[ks+tig][nn]);
                uint32_t b1 = __float_as_uint(Bs[ks+tig+4][nn]);
                mma_tf32(acc[0][nt], af[0], b0, b1);
                mma_tf32(acc[1][nt], af[1], b0, b1);
            }
        }
        __syncthreads();
    }
    #pragma unroll
    for (int mt = 0; mt < 2; mt++) {
        int row = row0 + wm*32 + mt*16 + grp;
        #pragma unroll
        for (int nt = 0; nt < 4; nt++) {
            int col = col0 + wn*32 + nt*8 + tig*2;
            float bx0 = (BIASMODE == 0) ? bias[col]   : bias[(row >> 13)*256 + col];
            float bx1 = (BIASMODE == 0) ? bias[col+1] : bias[(row >> 13)*256 + col + 1];
            float v0 = acc[mt][nt][0] + bx0, v1 = acc[mt][nt][1] + bx1;
            float v2 = acc[mt][nt][2] + bx0, v3 = acc[mt][nt][3] + bx1;
            if (RELU) {
                v0 = fmaxf(v0, 0.f); v1 = fmaxf(v1, 0.f);
                v2 = fmaxf(v2, 0.f); v3 = fmaxf(v3, 0.f);
            }
            *(float2*)&C[row*NT + col]       = make_float2(v0, v1);
            *(float2*)&C[(row+8)*NT + col]   = make_float2(v2, v3);
        }
    }
}

// ---------------- gather-max stage 1 (act2 tf32-rounded) ----------------
__global__ void gather1_kernel() {
    int wid  = (blockIdx.x * blockDim.x + threadIdx.x) >> 5;
    int lane = threadIdx.x & 31;
    if (wid >= NP) return;
    const int* idx = &g_idx[wid*KNN];
    float4 mv = make_float4(-3.4e38f, -3.4e38f, -3.4e38f, -3.4e38f);
    #pragma unroll
    for (int t = 0; t < KNN; t++) {
        int j = idx[t];
        float4 v = *(const float4*)&g_ac1[j*256 + 128 + lane*4];
        mv.x = fmaxf(mv.x, v.x); mv.y = fmaxf(mv.y, v.y);
        mv.z = fmaxf(mv.z, v.z); mv.w = fmaxf(mv.w, v.w);
    }
    float4 a = *(const float4*)&g_ac1[wid*256 + lane*4];
    float4 o;
    o.x = tf32r(fmaxf(a.x + mv.x, 0.f)); o.y = tf32r(fmaxf(a.y + mv.y, 0.f));
    o.z = tf32r(fmaxf(a.z + mv.z, 0.f)); o.w = tf32r(fmaxf(a.w + mv.w, 0.f));
    *(float4*)&g_act2[wid*144 + lane*4] = o;
    if (lane < 16) {
        float v = (lane < 3) ? tf32r(((const float*)g_coords4)[wid*4 + lane]) : 0.f;
        g_act2[wid*144 + 128 + lane] = v;
    }
}

// ---------------- gather-max stage 2 (f2 tf32-rounded) ----------------
__global__ void gather2_kernel() {
    int wid  = (blockIdx.x * blockDim.x + threadIdx.x) >> 5;
    int lane = threadIdx.x & 31;
    if (wid >= NP) return;
    const int* idx = &g_idx[wid*KNN];
    float4 m0 = make_float4(-3.4e38f, -3.4e38f, -3.4e38f, -3.4e38f);
    float4 m1 = m0;
    #pragma unroll
    for (int t = 0; t < KNN; t++) {
        int j = idx[t];
        float4 v0 = *(const float4*)&g_ac2[j*512 + 256 + lane*4];
        float4 v1 = *(const float4*)&g_ac2[j*512 + 384 + lane*4];
        m0.x = fmaxf(m0.x, v0.x); m0.y = fmaxf(m0.y, v0.y);
        m0.z = fmaxf(m0.z, v0.z); m0.w = fmaxf(m0.w, v0.w);
        m1.x = fmaxf(m1.x, v1.x); m1.y = fmaxf(m1.y, v1.y);
        m1.z = fmaxf(m1.z, v1.z); m1.w = fmaxf(m1.w, v1.w);
    }
    float4 a0 = *(const float4*)&g_ac2[wid*512 + lane*4];
    float4 a1 = *(const float4*)&g_ac2[wid*512 + 128 + lane*4];
    float4 o0, o1;
    o0.x = tf32r(fmaxf(a0.x + m0.x, 0.f)); o0.y = tf32r(fmaxf(a0.y + m0.y, 0.f));
    o0.z = tf32r(fmaxf(a0.z + m0.z, 0.f)); o0.w = tf32r(fmaxf(a0.w + m0.w, 0.f));
    o1.x = tf32r(fmaxf(a1.x + m1.x, 0.f)); o1.y = tf32r(fmaxf(a1.y + m1.y, 0.f));
    o1.z = tf32r(fmaxf(a1.z + m1.z, 0.f)); o1.w = tf32r(fmaxf(a1.w + m1.w, 0.f));
    *(float4*)&g_f2[wid*256 + lane*4]       = o0;
    *(float4*)&g_f2[wid*256 + 128 + lane*4] = o1;
}

// ---------------- global max pooling ----------------
__global__ void zero_gmax_kernel() {
    int i = threadIdx.x;
    if (i < NBATCH*256) g_gmax[i] = 0;   // 0.0f bits; all f2 >= 0
}

__global__ void colmax_kernel() {
    int b = blockIdx.x >> 5;
    int chunk = blockIdx.x & 31;
    int c = threadIdx.x;
    int base = b*NPTS + chunk*256;
    float m = 0.f;
    #pragma unroll 4
    for (int p = 0; p < 256; p++) m = fmaxf(m, g_f2[(base + p)*256 + c]);
    atomicMax(&g_gmax[b*256 + c], __float_as_int(m));
}

// ---------------- per-batch vectors ----------------
__global__ void batchvec_kernel(const float* __restrict__ globw, const float* __restrict__ globb,
                                const float* __restrict__ h1w, const float* __restrict__ h1b) {
    int b = blockIdx.x, n = threadIdx.x;
    __shared__ float gm[256], gg[256];
    gm[n] = __int_as_float(g_gmax[b*256 + n]);
    __syncthreads();
    float s = globb[n];
    #pragma unroll 8
    for (int k = 0; k < 256; k++) s = fmaf(gm[k], globw[k*256 + n], s);
    gg[n] = fmaxf(s, 0.f);
    __syncthreads();
    float t = h1b[n];
    #pragma unroll 8
    for (int k = 0; k < 256; k++) t = fmaf(gg[k], h1w[(256 + k)*256 + n], t);
    g_tvec[b*256 + n] = t;
}

// ---------------- final head ----------------
__global__ void final_kernel(const float* __restrict__ x,
                             const float* __restrict__ h2w, const float* __restrict__ h2b,
                             const float* __restrict__ pthresh, const float* __restrict__ psharp,
                             const float* __restrict__ pscale, float* __restrict__ out) {
    int wid  = (blockIdx.x * blockDim.x + threadIdx.x) >> 5;
    int lane = threadIdx.x & 31;
    if (wid >= NP) return;
    const float* h = &g_h[wid*256];
    float s0 = 0.f, s1 = 0.f, s2 = 0.f;
    #pragma unroll
    for (int m = 0; m < 8; m++) {
        int k = lane + 32*m;
        float hv = h[k];
        s0 = fmaf(hv, h2w[k*3+0], s0);
        s1 = fmaf(hv, h2w[k*3+1], s1);
        s2 = fmaf(hv, h2w[k*3+2], s2);
    }
    #pragma unroll
    for (int o = 16; o; o >>= 1) {
        s0 += __shfl_down_sync(0xFFFFFFFFu, s0, o);
        s1 += __shfl_down_sync(0xFFFFFFFFu, s1, o);
        s2 += __shfl_down_sync(0xFFFFFFFFu, s2, o);
    }
    if (lane == 0) {
        float hag = x[wid*4 + 3];
        float t = (*psharp) * ((*pthresh) - hag);
        float bias = (*pscale) / (1.f + expf(-t));
        out[wid*3+0] = s0 + h2b[0] + bias;
        out[wid*3+1] = s1 + h2b[1];
        out[wid*3+2] = s2 + h2b[2];
    }
}

// ---------------- launch ----------------
extern "C" void kernel_launch(void* const* d_in, const int* in_sizes, int n_in,
                              void* d_out, int out_size) {
    const float* x      = (const float*)d_in[0];
    const float* hmix_a = (const float*)d_in[1];
    const float* hmix_b = (const float*)d_in[2];
    const float* hmix_c = (const float*)d_in[3];
    const float* stem_w = (const float*)d_in[4];
    const float* stem_b = (const float*)d_in[5];
    const float* b1_w   = (const float*)d_in[6];
    const float* b1_b   = (const float*)d_in[7];
    const float* b2_w   = (const float*)d_in[8];
    const float* b2_b   = (const float*)d_in[9];
    const float* glob_w = (const float*)d_in[10];
    const float* glob_b = (const float*)d_in[11];
    const float* h1_w   = (const float*)d_in[12];
    const float* h1_b   = (const float*)d_in[13];
    const float* h2_w   = (const float*)d_in[14];
    const float* h2_b   = (const float*)d_in[15];
    const float* thresh = (const float*)d_in[16];
    const float* sharp  = (const float*)d_in[17];
    const float* scale  = (const float*)d_in[18];
    float* out = (float*)d_out;

    void *p_act1, *p_Wc1, *p_bc1, *p_ac1, *p_act2, *p_Wc2, *p_bc2, *p_ac2, *p_f2, *p_tvec, *p_h, *p_Wh1;
    cudaGetSymbolAddress(&p_act1, g_act1);
    cudaGetSymbolAddress(&p_Wc1,  g_Wc1);
    cudaGetSymbolAddress(&p_bc1,  g_bc1);
    cudaGetSymbolAddress(&p_ac1,  g_ac1);
    cudaGetSymbolAddress(&p_act2, g_act2);
    cudaGetSymbolAddress(&p_Wc2,  g_Wc2);
    cudaGetSymbolAddress(&p_bc2,  g_bc2);
    cudaGetSymbolAddress(&p_ac2,  g_ac2);
    cudaGetSymbolAddress(&p_f2,   g_f2);
    cudaGetSymbolAddress(&p_tvec, g_tvec);
    cudaGetSymbolAddress(&p_h,    g_h);
    cudaGetSymbolAddress(&p_Wh1,  g_Wh1);

    cudaFuncSetAttribute(knn_kernel, cudaFuncAttributeMaxDynamicSharedMemorySize, KNN_SMEM);

    build_weights<<<1, 256>>>(b1_w, b1_b, b2_w, b2_b, h1_w);
    prep_kernel<<<NP/256, 256>>>(x, hmix_a, hmix_b, hmix_c, stem_w, stem_b);
    zero_gmax_kernel<<<1, 1024>>>();
    knn_kernel<<<NBATCH*64, KT, KNN_SMEM>>>();

    gemm_kernel<80, 256, 0, 0><<<dim3(NP/128, 256/64), 256>>>(
        (const float*)p_act1, (const float*)p_Wc1, (const float*)p_bc1, (float*)p_ac1);
    gather1_kernel<<<NP*32/256, 256>>>();

    gemm_kernel<144, 512, 0, 0><<<dim3(NP/128, 512/64), 256>>>(
        (const float*)p_act2, (const float*)p_Wc2, (const float*)p_bc2, (float*)p_ac2);
    gather2_kernel<<<NP*32/256, 256>>>();

    colmax_kernel<<<NBATCH*32, 256>>>();
    batchvec_kernel<<<NBATCH, 256>>>(glob_w, glob_b, h1_w, h1_b);

    gemm_kernel<256, 256, 1, 1><<<dim3(NP/128, 256/64), 256>>>(
        (const float*)p_f2, (const float*)p_Wh1, (const float*)p_tvec, (float*)p_h);

    final_kernel<<<NP*32/256, 256>>>(x, h2_w, h2_b, thresh, sharp, scale, out);
    (void)in_sizes; (void)n_in; (void)out_size;
}